// round 5
// baseline (speedup 1.0000x reference)
#include <cuda_runtime.h>
#include <cuda_bf16.h>
#include <cstdint>

// Problem constants
#define BB   256   // batch
#define LL   256   // seq len
#define IN_  256   // input dim
#define DD   128   // hidden dim
#define HH   64    // DD/2

// ---------------------------------------------------------------------------
// packed f32x2 helpers (FFMA2)
// ---------------------------------------------------------------------------
__device__ __forceinline__ unsigned long long ffma2(unsigned long long a,
                                                    unsigned long long b,
                                                    unsigned long long c) {
    unsigned long long d;
    asm("fma.rn.f32x2 %0, %1, %2, %3;" : "=l"(d) : "l"(a), "l"(b), "l"(c));
    return d;
}
__device__ __forceinline__ float2 unpack2(unsigned long long v) {
    float2 f;
    asm("mov.b64 {%0, %1}, %2;" : "=f"(f.x), "=f"(f.y) : "l"(v));
    return f;
}
__device__ __forceinline__ unsigned int f2tf32(float f) {
    unsigned int u;
    asm("cvt.rna.tf32.f32 %0, %1;" : "=r"(u) : "f"(f));
    return u;
}

// ---------------------------------------------------------------------------
// Scratch (device globals; no runtime allocation allowed)
// ---------------------------------------------------------------------------
__device__ float g_X[(size_t)BB * LL * 384];  // [b][t][mat*128+d]
__device__ float g_a[(size_t)BB * LL];        // attention gate a[b][t]

// ---------------------------------------------------------------------------
// Kernel A: projection GEMM via tf32 mma.sync (m16n8k8).
//   grid.y 0..2 : gates r/z/h (BM=128, BN=128, BK=32, 512 thr)
//   grid.y == 3 : attention gate a[b][t] (folded in; runs concurrently)
// ---------------------------------------------------------------------------
#define PJ_STRIDE 36
extern __shared__ float pj_sm[];

__global__ __launch_bounds__(512, 1) void proj_gemm_tf32(
    const float* __restrict__ x,
    const float* __restrict__ wr, const float* __restrict__ br,
    const float* __restrict__ wz, const float* __restrict__ bz,
    const float* __restrict__ wh, const float* __restrict__ bh,
    const float* __restrict__ k1k2, float* __restrict__ ga,
    float* __restrict__ out)
{
    const int my  = blockIdx.y;
    const int tid = threadIdx.x;

    if (my == 3) {
        // ---- a-gate: 128 rows per block, 4 threads per row ----
        const int row = blockIdx.x * 128 + (tid >> 2);
        const int kq  = (tid & 3) * 64;
        const float* xr = x + (size_t)row * 256 + kq;
        const float* c1 = k1k2 + kq;
        const float* c2 = k1k2 + 256 + kq;
        float s = 0.f;
#pragma unroll
        for (int r = 0; r < 16; r++) {
            float4 xv = *(const float4*)&xr[r * 4];
            float4 a1 = *(const float4*)&c1[r * 4];
            float4 a2 = *(const float4*)&c2[r * 4];
            s += xv.x * (a1.x - a2.x) + xv.y * (a1.y - a2.y) +
                 xv.z * (a1.z - a2.z) + xv.w * (a1.w - a2.w);
        }
        s += __shfl_xor_sync(0xffffffffu, s, 1);
        s += __shfl_xor_sync(0xffffffffu, s, 2);
        if ((tid & 3) == 0)
            ga[row] = __fdividef(1.f, 1.f + __expf(-s));
        return;
    }

    float* As = pj_sm;                                // [2][128][36]
    float* Bs = pj_sm + 2 * 128 * PJ_STRIDE;          // [2][128][36]

    const float* __restrict__ W  = (my == 0) ? wr : (my == 1 ? wz : wh);
    const float* __restrict__ Bv = (my == 0) ? br : (my == 1 ? bz : bh);

    const int lane = tid & 31;
    const int wid  = tid >> 5;
    const int wm   = wid & 3;
    const int wn   = wid >> 2;
    const int gid  = lane >> 2;
    const int tid4 = lane & 3;
    const int i0   = blockIdx.x * 128;

    const int lr = tid >> 3;
    const int lc = tid & 7;

    float acc[2][4][4];
#pragma unroll
    for (int a = 0; a < 2; a++)
#pragma unroll
        for (int b = 0; b < 4; b++)
#pragma unroll
            for (int c = 0; c < 4; c++) acc[a][b][c] = 0.f;

    float4 sx0, sx1, sw0, sw1;

    {
        const int k0 = 0;
        sx0 = *(const float4*)&x[(size_t)(i0 + lr)      * 256 + k0 + lc * 4];
        sx1 = *(const float4*)&x[(size_t)(i0 + lr + 64) * 256 + k0 + lc * 4];
        sw0 = *(const float4*)&W[(size_t)(lr)      * 256 + k0 + lc * 4];
        sw1 = *(const float4*)&W[(size_t)(lr + 64) * 256 + k0 + lc * 4];
        unsigned int* a0 = (unsigned int*)&As[(size_t)lr * PJ_STRIDE + lc * 4];
        unsigned int* a1 = (unsigned int*)&As[(size_t)(lr + 64) * PJ_STRIDE + lc * 4];
        unsigned int* b0 = (unsigned int*)&Bs[(size_t)lr * PJ_STRIDE + lc * 4];
        unsigned int* b1 = (unsigned int*)&Bs[(size_t)(lr + 64) * PJ_STRIDE + lc * 4];
        a0[0]=f2tf32(sx0.x); a0[1]=f2tf32(sx0.y); a0[2]=f2tf32(sx0.z); a0[3]=f2tf32(sx0.w);
        a1[0]=f2tf32(sx1.x); a1[1]=f2tf32(sx1.y); a1[2]=f2tf32(sx1.z); a1[3]=f2tf32(sx1.w);
        b0[0]=f2tf32(sw0.x); b0[1]=f2tf32(sw0.y); b0[2]=f2tf32(sw0.z); b0[3]=f2tf32(sw0.w);
        b1[0]=f2tf32(sw1.x); b1[1]=f2tf32(sw1.y); b1[2]=f2tf32(sw1.z); b1[3]=f2tf32(sw1.w);
    }
    __syncthreads();

#pragma unroll 1
    for (int t = 0; t < 8; t++) {
        const int cur = t & 1;
        const int nxt = cur ^ 1;
        if (t < 7) {
            const int k0 = (t + 1) * 32;
            sx0 = *(const float4*)&x[(size_t)(i0 + lr)      * 256 + k0 + lc * 4];
            sx1 = *(const float4*)&x[(size_t)(i0 + lr + 64) * 256 + k0 + lc * 4];
            sw0 = *(const float4*)&W[(size_t)(lr)      * 256 + k0 + lc * 4];
            sw1 = *(const float4*)&W[(size_t)(lr + 64) * 256 + k0 + lc * 4];
        }

        const unsigned int* Au = (const unsigned int*)(As + (size_t)cur * 128 * PJ_STRIDE);
        const unsigned int* Bu = (const unsigned int*)(Bs + (size_t)cur * 128 * PJ_STRIDE);

#pragma unroll
        for (int ks = 0; ks < 4; ks++) {
            const int kb = ks * 8;
            unsigned int af[2][4];
#pragma unroll
            for (int mt = 0; mt < 2; mt++) {
                int row = wm * 32 + mt * 16 + gid;
                af[mt][0] = Au[(size_t)row * PJ_STRIDE + kb + tid4];
                af[mt][1] = Au[(size_t)(row + 8) * PJ_STRIDE + kb + tid4];
                af[mt][2] = Au[(size_t)row * PJ_STRIDE + kb + tid4 + 4];
                af[mt][3] = Au[(size_t)(row + 8) * PJ_STRIDE + kb + tid4 + 4];
            }
            unsigned int bf[4][2];
#pragma unroll
            for (int nt = 0; nt < 4; nt++) {
                int col = wn * 32 + nt * 8 + gid;
                bf[nt][0] = Bu[(size_t)col * PJ_STRIDE + kb + tid4];
                bf[nt][1] = Bu[(size_t)col * PJ_STRIDE + kb + tid4 + 4];
            }
#pragma unroll
            for (int mt = 0; mt < 2; mt++)
#pragma unroll
                for (int nt = 0; nt < 4; nt++) {
                    asm volatile(
                        "mma.sync.aligned.m16n8k8.row.col.f32.tf32.tf32.f32 "
                        "{%0,%1,%2,%3}, {%4,%5,%6,%7}, {%8,%9}, {%0,%1,%2,%3};"
                        : "+f"(acc[mt][nt][0]), "+f"(acc[mt][nt][1]),
                          "+f"(acc[mt][nt][2]), "+f"(acc[mt][nt][3])
                        : "r"(af[mt][0]), "r"(af[mt][1]),
                          "r"(af[mt][2]), "r"(af[mt][3]),
                          "r"(bf[nt][0]), "r"(bf[nt][1]));
                }
        }

        if (t < 7) {
            unsigned int* a0 = (unsigned int*)&As[((size_t)nxt * 128 + lr) * PJ_STRIDE + lc * 4];
            unsigned int* a1 = (unsigned int*)&As[((size_t)nxt * 128 + lr + 64) * PJ_STRIDE + lc * 4];
            unsigned int* b0 = (unsigned int*)&Bs[((size_t)nxt * 128 + lr) * PJ_STRIDE + lc * 4];
            unsigned int* b1 = (unsigned int*)&Bs[((size_t)nxt * 128 + lr + 64) * PJ_STRIDE + lc * 4];
            a0[0]=f2tf32(sx0.x); a0[1]=f2tf32(sx0.y); a0[2]=f2tf32(sx0.z); a0[3]=f2tf32(sx0.w);
            a1[0]=f2tf32(sx1.x); a1[1]=f2tf32(sx1.y); a1[2]=f2tf32(sx1.z); a1[3]=f2tf32(sx1.w);
            b0[0]=f2tf32(sw0.x); b0[1]=f2tf32(sw0.y); b0[2]=f2tf32(sw0.z); b0[3]=f2tf32(sw0.w);
            b1[0]=f2tf32(sw1.x); b1[1]=f2tf32(sw1.y); b1[2]=f2tf32(sw1.z); b1[3]=f2tf32(sw1.w);
        }
        __syncthreads();
    }

#pragma unroll
    for (int mt = 0; mt < 2; mt++) {
        int r0 = i0 + wm * 32 + mt * 16 + gid;
#pragma unroll
        for (int nt = 0; nt < 4; nt++) {
            int c0 = wn * 32 + nt * 8 + 2 * tid4;
            float2 bias = *(const float2*)&Bv[c0];
            float* p0 = &out[(size_t)r0 * 384 + my * 128 + c0];
            float* p1 = &out[(size_t)(r0 + 8) * 384 + my * 128 + c0];
            *(float2*)p0 = make_float2(acc[mt][nt][0] + bias.x,
                                       acc[mt][nt][1] + bias.y);
            *(float2*)p1 = make_float2(acc[mt][nt][2] + bias.x,
                                       acc[mt][nt][3] + bias.y);
        }
    }
}

// ---------------------------------------------------------------------------
// Kernel B v4: sequential recurrence. 128 CTAs x 2 batches, 256 threads.
//   tid = 2*d + q.  q = k-half and (for update) batch.
//   m loads are direct ulonglong2 (no pack movs); m layout padded to 68-float
//   halves so the warp's two broadcast lines hit disjoint banks (1 wavefront).
//   3 shuffles/step (send partner its batch's partial). One barrier/step.
// ---------------------------------------------------------------------------
// m_sm layout: [parity][batch][half q][68]  -> 2*2*2*68 = 544 floats
#define MPAR 272   // floats per parity
#define MBAT 136   // floats per batch
#define MHALF 68   // floats per k-half (64 data + 4 pad)

__global__ __launch_bounds__(256, 1) void rnn_kernel(
    const float* __restrict__ gX, const float* __restrict__ ga,
    const int* __restrict__ cor,
    const float* __restrict__ ur, const float* __restrict__ uz,
    const float* __restrict__ uh,
    float* __restrict__ out)
{
    extern __shared__ float sm[];
    float* m_sm   = sm;                    // [2][2][2][68]          544
    float* a_sm   = sm + 544;              // [2][256]               512
    int*   cor_sm = (int*)(sm + 1056);     // [2][256]               512
    float* buf    = sm + 1568;             // [2][257][64]           32896

    const int tid = threadIdx.x;
    const int q   = tid & 1;      // k-half; also batch handled in update
    const int d   = tid >> 1;     // 0..127
    const int b0  = blockIdx.x * 2;
    const int kb  = q * 64;

    // ---- U register cache: rows d of u_r/u_z/u_h, k in [kb, kb+64) ----
    unsigned long long urr[32], uzr[32], uhr[32];
#pragma unroll
    for (int j = 0; j < 32; j++) {
        urr[j] = *(const unsigned long long*)&ur[d * 128 + kb + 2 * j];
        uzr[j] = *(const unsigned long long*)&uz[d * 128 + kb + 2 * j];
        uhr[j] = *(const unsigned long long*)&uh[d * 128 + kb + 2 * j];
    }

    // ---- init ----
#pragma unroll
    for (int i = tid; i < 544; i += 256) m_sm[i] = 0.f;
    if (tid < 128) buf[(tid >> 6) * 16448 + (tid & 63)] = 0.f;
#pragma unroll
    for (int i = tid; i < 512; i += 256) {
        int bb = i >> 8, tt = i & 255;
        a_sm[i]   = ga[(size_t)(b0 + bb) * LL + tt];
        cor_sm[i] = cor[(size_t)(b0 + bb) * LL + tt];
    }
    __syncthreads();

    // prefetch X for t=0, batch q
    size_t xbase = ((size_t)(b0 + q) * LL) * 384 + d;
    float xr = gX[xbase], xz = gX[xbase + 128], xh = gX[xbase + 256];

    for (int t = 0; t < LL; t++) {
        const int par = t & 1;
        const int np  = par ^ 1;

        // ---- matvec over k-half [kb,kb+64), both batches ----
        const ulonglong2* p0 =
            (const ulonglong2*)(m_sm + par * MPAR + q * MHALF);           // batch 0
        const ulonglong2* p1 =
            (const ulonglong2*)(m_sm + par * MPAR + MBAT + q * MHALF);    // batch 1
        unsigned long long ar0 = 0ULL, az0 = 0ULL, ah0 = 0ULL;
        unsigned long long ar1 = 0ULL, az1 = 0ULL, ah1 = 0ULL;
#pragma unroll
        for (int j = 0; j < 16; j++) {
            ulonglong2 v0 = p0[j];
            ulonglong2 v1 = p1[j];
            ar0 = ffma2(urr[2*j],   v0.x, ar0);
            az0 = ffma2(uzr[2*j],   v0.x, az0);
            ah0 = ffma2(uhr[2*j],   v0.x, ah0);
            ar1 = ffma2(urr[2*j],   v1.x, ar1);
            az1 = ffma2(uzr[2*j],   v1.x, az1);
            ah1 = ffma2(uhr[2*j],   v1.x, ah1);
            ar0 = ffma2(urr[2*j+1], v0.y, ar0);
            az0 = ffma2(uzr[2*j+1], v0.y, az0);
            ah0 = ffma2(uhr[2*j+1], v0.y, ah0);
            ar1 = ffma2(urr[2*j+1], v1.y, ar1);
            az1 = ffma2(uzr[2*j+1], v1.y, az1);
            ah1 = ffma2(uhr[2*j+1], v1.y, ah1);
        }

        // horizontal add; exchange: each lane sends its partial of the
        // OTHER batch, receives partner's partial of ITS batch.
        float2 f;
        f = unpack2(ar0); float sr0 = f.x + f.y;
        f = unpack2(az0); float sz0 = f.x + f.y;
        f = unpack2(ah0); float sh0 = f.x + f.y;
        f = unpack2(ar1); float sr1 = f.x + f.y;
        f = unpack2(az1); float sz1 = f.x + f.y;
        f = unpack2(ah1); float sh1 = f.x + f.y;

        float sr = (q ? sr1 : sr0) + __shfl_xor_sync(0xffffffffu, q ? sr0 : sr1, 1);
        float sz = (q ? sz1 : sz0) + __shfl_xor_sync(0xffffffffu, q ? sz0 : sz1, 1);
        float sh = (q ? sh1 : sh0) + __shfl_xor_sync(0xffffffffu, q ? sh0 : sh1, 1);

        // ---- nonlinearity + state update (all 256 threads) ----
        float r  = __fdividef(1.f, 1.f + __expf(-(xr + sr)));
        float z  = __fdividef(1.f, 1.f + __expf(-(xz + sz)));
        float ey = __expf(2.f * (xh + r * sh));
        float hv = 1.f - __fdividef(2.f, ey + 1.f);
        float mv = m_sm[par * MPAR + q * MBAT + (d < HH ? d : MHALF + d - HH)];
        float h  = (1.f - z) * mv + z * hv;

        out[(((size_t)(b0 + q) * LL) + t) * DD + d] = h;

        if (t + 1 < LL) {
            // prefetch X for t+1 (consumed ~1 step later)
            xbase = ((size_t)(b0 + q) * LL + (t + 1)) * 384 + d;
            xr = gX[xbase]; xz = gX[xbase + 128]; xh = gX[xbase + 256];

            float an = a_sm[q * 256 + t + 1];
            if (d < HH) {
                m_sm[np * MPAR + q * MBAT + d] = an * h;
            } else {
                buf[q * 16448 + (t + 1) * 64 + (d - HH)] = h;
                int cn = cor_sm[q * 256 + t + 1];
                int ie = (cn == 0) ? (t + 1) : cn;
                m_sm[np * MPAR + q * MBAT + MHALF + (d - HH)] =
                    (1.f - an) * buf[q * 16448 + ie * 64 + (d - HH)];
            }
        }
        __syncthreads();
    }
}

// ---------------------------------------------------------------------------
// launch
// ---------------------------------------------------------------------------
extern "C" void kernel_launch(void* const* d_in, const int* in_sizes, int n_in,
                              void* d_out, int out_size)
{
    (void)in_sizes; (void)n_in; (void)out_size;
    const float* x    = (const float*)d_in[0];
    const int*   cor  = (const int*)d_in[1];
    const float* w_r  = (const float*)d_in[2];
    const float* b_r  = (const float*)d_in[3];
    const float* u_r  = (const float*)d_in[4];
    const float* w_z  = (const float*)d_in[5];
    const float* b_z  = (const float*)d_in[6];
    const float* u_z  = (const float*)d_in[7];
    const float* w_h  = (const float*)d_in[8];
    const float* b_h  = (const float*)d_in[9];
    const float* u_h  = (const float*)d_in[10];
    const float* k1k2 = (const float*)d_in[11];
    float* out = (float*)d_out;

    float* gX; cudaGetSymbolAddress((void**)&gX, g_X);
    float* ga; cudaGetSymbolAddress((void**)&ga, g_a);

    // Kernel A: projections via tf32 tensor cores (+ a-gate blocks at gy=3)
    {
        const int smemA = 2 * 2 * 128 * PJ_STRIDE * 4;   // 73728 B
        cudaFuncSetAttribute(proj_gemm_tf32,
                             cudaFuncAttributeMaxDynamicSharedMemorySize, smemA);
        dim3 grid(BB * LL / 128, 4);
        proj_gemm_tf32<<<grid, 512, smemA>>>(x, w_r, b_r, w_z, b_z, w_h, b_h,
                                             k1k2, ga, gX);
    }

    // Kernel B: recurrence
    {
        const size_t smemB = (size_t)(544 + 512 + 512 + 2 * 257 * 64)
                             * sizeof(float);            // 137856 B
        cudaFuncSetAttribute(rnn_kernel,
                             cudaFuncAttributeMaxDynamicSharedMemorySize,
                             (int)smemB);
        rnn_kernel<<<128, 256, smemB>>>(gX, ga, cor, u_r, u_z, u_h, out);
    }
}